// round 15
// baseline (speedup 1.0000x reference)
#include <cuda_runtime.h>
#include <math.h>

#define NN  200000
#define KK  16
#define GG  4000
#define NPG 50
#define EPS 1e-5f

#define NG1 (NN / 8)
#define NG2 (NN / 16)
#define CGRID1 444      // conv1: 148 SMs * 3 blocks
#define CGRID2 444      // conv2: 148 SMs * 3 blocks

#define CP16(dst, src) asm volatile("cp.async.cg.shared.global [%0], [%1], 16;" :: "r"(dst), "l"(src) : "memory")
#define CP_COMMIT()    asm volatile("cp.async.commit_group;" ::: "memory")
#define CP_WAIT2()     asm volatile("cp.async.wait_group 2;" ::: "memory")
#define CP_WAIT1()     asm volatile("cp.async.wait_group 1;" ::: "memory")
#define CP_WAIT0()     asm volatile("cp.async.wait_group 0;" ::: "memory")

// ---------------- scratch ----------------
__device__ float g_B1[NN * 32];
__device__ float g_D1[NN * 16];
__device__ float g_B2[NN * 16];
__device__ float g_D2[NN * 8];
__device__ float g_pooled[GG * 8];
__device__ unsigned g_ctr = 0;

// folded ab1 weights
__device__ float g_ws1[25 * 28];
__device__ float g_cs1[16 * 28];
__device__ float g_c01[16];

// =================================================================
// kernel 0: one-block fold for ab1's weights
// =================================================================
__global__ void fold_kernel(
    const float* __restrict__ w1_pre, const float* __restrict__ b1_pre,
    const float* __restrict__ w1_post, const float* __restrict__ b1_post,
    const float* __restrict__ w1_lin,  const float* __restrict__ b1_lin)
{
    __shared__ float pa[16 * 25];
    __shared__ float pb[16 * 25];
    int t = threadIdx.x;

    for (int i = t; i < 16 * 25; i += 256) {
        int k = i / 25, jj = i % 25;
        const float* pr = w1_post + k * 300;
        pa[i] = pr[jj] + pr[25 + jj] + pr[50 + jj]
              + pr[100 + jj] + pr[125 + jj] + pr[150 + jj]
              + pr[200 + jj] + pr[225 + jj] + pr[250 + jj];
    }
    __syncthreads();
    for (int i = t; i < 16 * 25; i += 256) {
        int o = i / 25, jj = i % 25;
        float s = 0.f;
        for (int k = 0; k < 16; k++) s = fmaf(w1_lin[o * 16 + k], pa[k * 25 + jj], s);
        pb[i] = s;
    }
    __syncthreads();
    for (int i = t; i < 16 * 28; i += 256) {
        int o = i / 28, ii = i % 28;
        float s = 0.f;
        if (ii < 25) { for (int j = 0; j < 25; j++) s = fmaf(pb[o * 25 + j], w1_pre[j * 50 + ii], s); }
        g_cs1[i] = s;
    }
    for (int i = t; i < 25 * 28; i += 256) {
        int j = i / 28, ii = i % 28;
        g_ws1[i] = (ii < 25) ? w1_pre[j * 50 + 25 + ii] : 0.f;
    }
    if (t < 16) {
        float s = b1_lin[t];
        for (int k = 0; k < 16; k++) s = fmaf(w1_lin[t * 16 + k], b1_post[k], s);
        for (int j = 0; j < 25; j++) s = fmaf(pb[t * 25 + j], b1_pre[j], s);
        g_c01[t] = s;
    }
}

// =================================================================
// kernel 1: ab1 — lean, folded weights from global; zeros g_pooled.
// (identical to R13)
// =================================================================
__global__ void __launch_bounds__(128) ab1_kernel(const float* __restrict__ x)
{
    __shared__ __align__(16) float xs[128 * 28];
    __shared__ __align__(16) float ws[25 * 28];
    __shared__ __align__(16) float cs[16 * 28];
    __shared__ float c0s[16];

    int t = threadIdx.x;
    int base = blockIdx.x * 128;
    int nvalid = NN - base; if (nvalid > 128) nvalid = 128;

    if (blockIdx.x < 250) g_pooled[blockIdx.x * 128 + t] = 0.f;

    for (int i = t; i < 25 * 28; i += 128) ws[i] = g_ws1[i];
    for (int i = t; i < 16 * 28; i += 128) cs[i] = g_cs1[i];
    if (t < 16) c0s[t] = g_c01[t];
    for (int i = t; i < nvalid * 25; i += 128) xs[(i / 25) * 28 + (i % 25)] = x[base * 25 + i];
    for (int i = t; i < nvalid * 3; i += 128) xs[(i / 3) * 28 + 25 + (i % 3)] = 0.f;
    __syncthreads();

    bool act = (t < nvalid);
    float4 xr[7];
    if (act) {
        const float4* xp = (const float4*)&xs[t * 28];
#pragma unroll
        for (int i = 0; i < 7; i++) xr[i] = xp[i];
    }
    __syncthreads();

    if (act) {
        const float4* wp = (const float4*)ws;
#pragma unroll
        for (int j = 0; j < 25; j++) {
            float4 a = make_float4(0.f, 0.f, 0.f, 0.f);
#pragma unroll
            for (int i = 0; i < 7; i++) {
                float4 w4 = wp[j * 7 + i];
                a.x = fmaf(w4.x, xr[i].x, a.x); a.y = fmaf(w4.y, xr[i].y, a.y);
                a.z = fmaf(w4.z, xr[i].z, a.z); a.w = fmaf(w4.w, xr[i].w, a.w);
            }
            xs[t * 28 + j] = (a.x + a.y) + (a.z + a.w);
        }
    }
    __syncthreads();
    for (int i = t; i < nvalid * 32; i += 128) {
        int nd = i >> 5, c = i & 31;
        if (c < 25) g_B1[(base + nd) * 32 + c] = xs[nd * 28 + c];
    }
    __syncthreads();

    if (act) {
        const float4* cp = (const float4*)cs;
#pragma unroll
        for (int o = 0; o < 16; o++) {
            float4 a = make_float4(0.f, 0.f, 0.f, 0.f);
#pragma unroll
            for (int i = 0; i < 7; i++) {
                float4 w4 = cp[o * 7 + i];
                a.x = fmaf(w4.x, xr[i].x, a.x); a.y = fmaf(w4.y, xr[i].y, a.y);
                a.z = fmaf(w4.z, xr[i].z, a.z); a.w = fmaf(w4.w, xr[i].w, a.w);
            }
            xs[t * 16 + o] = c0s[o] + (a.x + a.y) + (a.z + a.w);
        }
    }
    __syncthreads();
    for (int i = t; i < nvalid * 16; i += 128) g_D1[base * 16 + i] = xs[i];
}

// ---- gather helpers ----
__device__ __forceinline__ void gather_b1(unsigned dst, int sv, int lane)
{
#pragma unroll
    for (int ph = 0; ph < 4; ph++) {
        int c = ph * 32 + lane;
        int s = __shfl_sync(0xffffffffu, sv, c >> 3);
        CP16(dst + c * 16, &g_B1[s * 32 + (c & 7) * 4]);
    }
    CP_COMMIT();
}
__device__ __forceinline__ void gather_b2(unsigned dst, int sv, int lane)
{
#pragma unroll
    for (int ph = 0; ph < 4; ph++) {
        int c = ph * 32 + lane;
        int e = c >> 2;
        int s = __shfl_sync(0xffffffffu, sv, e);
        int row = e + (e >> 4);           // pad row between node halves
        CP16(dst + row * 64 + (c & 3) * 16, &g_B2[s * 16 + (c & 3) * 4]);
    }
    CP_COMMIT();
}

// =================================================================
// kernel 2: conv1 — 3-deep cp.async ring (dynamic smem), W in regs.
// stats -> matvec -> h1 -> fused ab2 -> B2/D2.
// =================================================================
__global__ void __launch_bounds__(256, 3) conv1_kernel(
    const int* __restrict__ src,
    const float* __restrict__ w1_post, const float* __restrict__ w1_lin,
    const float* __restrict__ w2_pre, const float* __restrict__ b2_pre,
    const float* __restrict__ w2_post, const float* __restrict__ b2_post,
    const float* __restrict__ w2_lin,  const float* __restrict__ b2_lin)
{
    extern __shared__ __align__(16) float s_dyn[];      // 8 warps x 3 bufs x 512 floats
    __shared__ __align__(16) float s_w1[16 * 108];
    __shared__ __align__(16) float s_agg[8][112];
    __shared__ __align__(16) float4 s_wb[4 * 32];
    __shared__ __align__(16) float s_h1[8][16];
    __shared__ float s_c02[8];

    int t = threadIdx.x;
    float* s_pa  = s_dyn;                 // preamble overlay
    float* s_p92 = s_pa + 1600;
    float* s_wa2 = s_p92 + 128;
    float* s_c2m = s_wa2 + 128;

    for (int i = t; i < 16 * 100; i += 256) {
        int k = i / 100, j = i % 100;
        s_pa[i] = w1_post[k * 300 + j] + w1_post[k * 300 + 100 + j] + w1_post[k * 300 + 200 + j];
    }
    for (int i = t; i < 8 * 16; i += 256) {
        int k = i / 16, jj = i % 16;
        const float* pr = w2_post + k * 192;
        s_p92[i] = pr[jj] + pr[16 + jj] + pr[32 + jj]
                 + pr[64 + jj] + pr[80 + jj] + pr[96 + jj]
                 + pr[128 + jj] + pr[144 + jj] + pr[160 + jj];
    }
    for (int i = t; i < 8 * 112; i += 256) ((float*)s_agg)[i] = 0.f;
    __syncthreads();
    for (int i = t; i < 16 * 108; i += 256) {
        int o = i / 108, j = i % 108;
        float s = 0.f;
        if (j < 100) { for (int k = 0; k < 16; k++) s = fmaf(w1_lin[o * 16 + k], s_pa[k * 100 + j], s); }
        s_w1[i] = s;
    }
    for (int i = t; i < 8 * 16; i += 256) {
        int o = i / 16, jj = i % 16;
        float s = 0.f;
        for (int k = 0; k < 8; k++) s = fmaf(w2_lin[o * 8 + k], s_p92[k * 16 + jj], s);
        s_wa2[i] = s;
    }
    __syncthreads();
    for (int i = t; i < 8 * 16; i += 256) {
        int o = i / 16, ii = i % 16;
        float s = 0.f;
        for (int j = 0; j < 16; j++) s = fmaf(s_wa2[o * 16 + j], w2_pre[j * 32 + ii], s);
        s_c2m[i] = s;
    }
    if (t < 8) {
        float s = b2_lin[t];
        for (int k = 0; k < 8; k++) s = fmaf(w2_lin[t * 8 + k], b2_post[k], s);
        for (int j = 0; j < 16; j++) s = fmaf(s_wa2[t * 16 + j], b2_pre[j], s);
        s_c02[t] = s;
    }
    __syncthreads();
    for (int i = t; i < 4 * 32; i += 256) {
        int i4 = i / 32, l = i % 32;
        float4 v = make_float4(0.f, 0.f, 0.f, 0.f);
        if (l < 16) {
            v.x = w2_pre[l * 32 + 16 + i4 * 4 + 0];
            v.y = w2_pre[l * 32 + 16 + i4 * 4 + 1];
            v.z = w2_pre[l * 32 + 16 + i4 * 4 + 2];
            v.w = w2_pre[l * 32 + 16 + i4 * 4 + 3];
        } else if (l < 24) {
            int o = l - 16;
            v.x = s_c2m[o * 16 + i4 * 4 + 0];
            v.y = s_c2m[o * 16 + i4 * 4 + 1];
            v.z = s_c2m[o * 16 + i4 * 4 + 2];
            v.w = s_c2m[o * 16 + i4 * 4 + 3];
        }
        s_wb[i] = v;
    }
    __syncthreads();   // dynamic stage free after this point

    int w = t >> 5, lane = t & 31;
    int o = lane & 15, hf = lane >> 4;

    float4 Wr[13];
    {
        const float4* wrow = (const float4*)&s_w1[o * 108 + hf * 52];
#pragma unroll
        for (int j = 0; j < 13; j++) Wr[j] = wrow[j];
    }

    unsigned c0 = (unsigned)__cvta_generic_to_shared(&s_dyn[(w * 3 + 0) * 512]);
    unsigned c1 = (unsigned)__cvta_generic_to_shared(&s_dyn[(w * 3 + 1) * 512]);
    unsigned c2 = (unsigned)__cvta_generic_to_shared(&s_dyn[(w * 3 + 2) * 512]);

    int lane15 = lane & 15;
    int g = blockIdx.x;
    // prologue: issue gathers for g and g+1; prefetch scalars up to g+2
    int sv = __ldg(&src[(g * 8 + w) * 16 + lane15]);
    gather_b1(c0, sv, lane);
    float d1_0 = (lane < 16) ? __ldg(&g_D1[(g * 8 + w) * 16 + lane]) : 0.f;
    float d1_1 = 0.f, d1_2 = 0.f;
    int g1 = g + CGRID1;
    if (g1 < NG1) {
        sv = __ldg(&src[(g1 * 8 + w) * 16 + lane15]);
        gather_b1(c1, sv, lane);
        if (lane < 16) d1_1 = __ldg(&g_D1[(g1 * 8 + w) * 16 + lane]);
    }
    int g2 = g1 + CGRID1;
    if (g2 < NG1) {
        sv = __ldg(&src[(g2 * 8 + w) * 16 + lane15]);
        if (lane < 16) d1_2 = __ldg(&g_D1[(g2 * 8 + w) * 16 + lane]);
    }

    while (true) {
        bool v1 = (g + CGRID1 < NG1);
        bool v2 = (g + 2 * CGRID1 < NG1);
        if (v2) gather_b1(c2, sv, lane);          // gather for g+2
        int g3 = g + 3 * CGRID1;
        float d1_3 = 0.f;
        if (g3 < NG1) {
            sv = __ldg(&src[(g3 * 8 + w) * 16 + lane15]);
            if (lane < 16) d1_3 = __ldg(&g_D1[(g3 * 8 + w) * 16 + lane]);
        }
        if (v2) CP_WAIT2(); else if (v1) CP_WAIT1(); else CP_WAIT0();
        __syncwarp();

        const float* sg = (const float*)&s_dyn[0] + ((c0 - (unsigned)__cvta_generic_to_shared(&s_dyn[0])) >> 2);
        if (lane < 25) {
            float sa = 0.f, sb = 0.f, qa = 0.f, qb = 0.f;
            float mna = 1e30f, mnb = 1e30f, mxa = -1e30f, mxb = -1e30f;
#pragma unroll
            for (int e = 0; e < 16; e += 2) {
                float a = sg[e * 32 + lane];
                float bq = sg[(e + 1) * 32 + lane];
                sa += a;  qa = fmaf(a, a, qa);  mna = fminf(mna, a);  mxa = fmaxf(mxa, a);
                sb += bq; qb = fmaf(bq, bq, qb); mnb = fminf(mnb, bq); mxb = fmaxf(mxb, bq);
            }
            float sum = sa + sb, sq = qa + qb;
            float mn = fminf(mna, mnb), mx = fmaxf(mxa, mxb);
            float mean = sum * (1.f / 16.f), m2 = sq * (1.f / 16.f);
            float st = sqrtf(fmaxf(m2 - mean * mean, 0.f) + EPS);
            s_agg[w][lane]      = mean;
            s_agg[w][25 + lane] = mn;
            s_agg[w][50 + lane] = mx;
            s_agg[w][75 + lane] = st;
        }
        __syncwarp();
        int n = g * 8 + w;
        {
            const float4* ar = (const float4*)&s_agg[w][hf * 52];
            float4 a4 = make_float4(0.f, 0.f, 0.f, 0.f);
#pragma unroll
            for (int j = 0; j < 13; j++) {
                float4 av = ar[j];
                a4.x = fmaf(Wr[j].x, av.x, a4.x); a4.y = fmaf(Wr[j].y, av.y, a4.y);
                a4.z = fmaf(Wr[j].z, av.z, a4.z); a4.w = fmaf(Wr[j].w, av.w, a4.w);
            }
            float p = (a4.x + a4.y) + (a4.z + a4.w);
            p += __shfl_xor_sync(0xffffffffu, p, 16);
            if (lane < 16) s_h1[w][lane] = fmaxf(p + d1_0, 0.f);
        }
        __syncwarp();
        {
            float acc = (lane >= 16 && lane < 24) ? s_c02[lane - 16] : 0.f;
            const float4* h4 = (const float4*)&s_h1[w][0];
#pragma unroll
            for (int i4 = 0; i4 < 4; i4++) {
                float4 hv = h4[i4];
                float4 wv = s_wb[i4 * 32 + lane];
                acc = fmaf(wv.x, hv.x, acc); acc = fmaf(wv.y, hv.y, acc);
                acc = fmaf(wv.z, hv.z, acc); acc = fmaf(wv.w, hv.w, acc);
            }
            if (lane < 16)      g_B2[n * 16 + lane] = acc;
            else if (lane < 24) g_D2[n * 8 + lane - 16] = acc;
        }
        // no trailing syncwarp: stage reads (stats) of this iter are fenced
        // by the stats-syncwarp before next iter's gather into old c0.

        if (!v1) break;
        g += CGRID1;
        d1_0 = d1_1; d1_1 = d1_2; d1_2 = d1_3;
        unsigned tmp = c0; c0 = c1; c1 = c2; c2 = tmp;
    }
}

// =================================================================
// kernel 3: conv2 — 3-deep cp.async ring (dynamic smem), W in regs,
// 2 nodes/warp; fused pooling + final FC.
// =================================================================
__global__ void __launch_bounds__(256, 3) conv2_kernel(
    const int* __restrict__ src,
    const float* __restrict__ w2_post, const float* __restrict__ w2_lin,
    const float* __restrict__ fc_w, const float* __restrict__ fc_b,
    float* __restrict__ out)
{
    extern __shared__ __align__(16) float s_dyn[];      // 8 warps x 3 bufs x 528 floats
    __shared__ __align__(16) float s_w2[8 * 72];
    __shared__ __align__(16) float s_agg[8][2][72];
    __shared__ unsigned s_rank;

    int t = threadIdx.x;
    float* s_pa = s_dyn;   // preamble overlay

    for (int i = t; i < 8 * 64; i += 256) {
        int k = i / 64, j = i % 64;
        s_pa[i] = w2_post[k * 192 + j] + w2_post[k * 192 + 64 + j] + w2_post[k * 192 + 128 + j];
    }
    for (int i = t; i < 8 * 72; i += 256) s_w2[i] = 0.f;
    for (int i = t; i < 8 * 2 * 72; i += 256) ((float*)s_agg)[i] = 0.f;
    __syncthreads();
    for (int i = t; i < 8 * 64; i += 256) {
        int o = i / 64, j = i % 64;
        float s = 0.f;
        for (int k = 0; k < 8; k++) s = fmaf(w2_lin[o * 8 + k], s_pa[k * 64 + j], s);
        int bq = j >> 4, r = j & 15;
        const int off[4] = {0, 16, 36, 52};
        s_w2[o * 72 + off[bq] + r] = s;
    }
    __syncthreads();

    int w = t >> 5, lane = t & 31;
    int node = lane >> 4, r = lane & 15;
    int o = r >> 1, hf = r & 1;

    float4 Wr[8];
    {
        const float4* wrow = (const float4*)&s_w2[o * 72 + hf * 36];
#pragma unroll
        for (int j = 0; j < 8; j++) Wr[j] = wrow[j];
    }

    unsigned c0 = (unsigned)__cvta_generic_to_shared(&s_dyn[(w * 3 + 0) * 528]);
    unsigned c1 = (unsigned)__cvta_generic_to_shared(&s_dyn[(w * 3 + 1) * 528]);
    unsigned c2 = (unsigned)__cvta_generic_to_shared(&s_dyn[(w * 3 + 2) * 528]);
    unsigned sbase = (unsigned)__cvta_generic_to_shared(&s_dyn[0]);

    int g = blockIdx.x;
    int sv = __ldg(&src[(g * 8 + w) * 32 + lane]);
    gather_b2(c0, sv, lane);
    float d2_0 = (hf == 0) ? __ldg(&g_D2[((g * 8 + w) * 2 + node) * 8 + o]) : 0.f;
    float d2_1 = 0.f, d2_2 = 0.f;
    int g1 = g + CGRID2;
    if (g1 < NG2) {
        sv = __ldg(&src[(g1 * 8 + w) * 32 + lane]);
        gather_b2(c1, sv, lane);
        if (hf == 0) d2_1 = __ldg(&g_D2[((g1 * 8 + w) * 2 + node) * 8 + o]);
    }
    int g2 = g1 + CGRID2;
    if (g2 < NG2) {
        sv = __ldg(&src[(g2 * 8 + w) * 32 + lane]);
        if (hf == 0) d2_2 = __ldg(&g_D2[((g2 * 8 + w) * 2 + node) * 8 + o]);
    }

    while (true) {
        bool v1 = (g + CGRID2 < NG2);
        bool v2 = (g + 2 * CGRID2 < NG2);
        if (v2) gather_b2(c2, sv, lane);
        int g3 = g + 3 * CGRID2;
        float d2_3 = 0.f;
        if (g3 < NG2) {
            sv = __ldg(&src[(g3 * 8 + w) * 32 + lane]);
            if (hf == 0) d2_3 = __ldg(&g_D2[((g3 * 8 + w) * 2 + node) * 8 + o]);
        }
        if (v2) CP_WAIT2(); else if (v1) CP_WAIT1(); else CP_WAIT0();
        __syncwarp();

        const float* sg = (const float*)&s_dyn[0] + ((c0 - sbase) >> 2);
        {
            int f = lane & 15;
            int rb = (lane >> 4) ? 17 : 0;
            float sa = 0.f, sb = 0.f, qa = 0.f, qb = 0.f;
            float mna = 1e30f, mnb = 1e30f, mxa = -1e30f, mxb = -1e30f;
#pragma unroll
            for (int e = 0; e < 16; e += 2) {
                float a = sg[(rb + e) * 16 + f];
                float bq = sg[(rb + e + 1) * 16 + f];
                sa += a;  qa = fmaf(a, a, qa);  mna = fminf(mna, a);  mxa = fmaxf(mxa, a);
                sb += bq; qb = fmaf(bq, bq, qb); mnb = fminf(mnb, bq); mxb = fmaxf(mxb, bq);
            }
            float sum = sa + sb, sq = qa + qb;
            float mn = fminf(mna, mnb), mx = fmaxf(mxa, mxb);
            float mean = sum * (1.f / 16.f), m2 = sq * (1.f / 16.f);
            float st = sqrtf(fmaxf(m2 - mean * mean, 0.f) + EPS);
            int nd = lane >> 4;
            s_agg[w][nd][f]      = mean;
            s_agg[w][nd][16 + f] = mn;
            s_agg[w][nd][36 + f] = mx;
            s_agg[w][nd][52 + f] = st;
        }
        __syncwarp();
        int nA = (g * 8 + w) * 2;
        {
            const float4* ar = (const float4*)&s_agg[w][node][hf * 36];
            float4 a4 = make_float4(0.f, 0.f, 0.f, 0.f);
#pragma unroll
            for (int j = 0; j < 8; j++) {
                float4 av = ar[j];
                a4.x = fmaf(Wr[j].x, av.x, a4.x); a4.y = fmaf(Wr[j].y, av.y, a4.y);
                a4.z = fmaf(Wr[j].z, av.z, a4.z); a4.w = fmaf(Wr[j].w, av.w, a4.w);
            }
            float p = (a4.x + a4.y) + (a4.z + a4.w);
            p += __shfl_xor_sync(0xffffffffu, p, 1);
            if (hf == 0) {
                float h = fmaxf(p + d2_0, 0.f);
                atomicAdd(&g_pooled[((nA + node) / NPG) * 8 + o], h);
            }
        }
        __syncwarp();   // needed: matvec reads s_agg; next stats rewrites it,
                        // and only this sync + wait-sync separate them safely
                        // across the atomic path divergence.

        if (!v1) break;
        g += CGRID2;
        d2_0 = d2_1; d2_1 = d2_2; d2_2 = d2_3;
        unsigned tmp = c0; c0 = c1; c1 = c2; c2 = tmp;
    }

    // ---- fused final: last block computes FC + log_softmax ----
    __syncthreads();
    __threadfence();
    if (t == 0) s_rank = atomicAdd(&g_ctr, 1u);
    __syncthreads();
    if (s_rank == (unsigned)(gridDim.x - 1)) {
        if (t == 0) g_ctr = 0;
        float w0[8], w1[8];
#pragma unroll
        for (int j = 0; j < 8; j++) { w0[j] = fc_w[j]; w1[j] = fc_w[8 + j]; }
        float b0 = fc_b[0], b1 = fc_b[1];
        for (int gg2 = t; gg2 < GG; gg2 += 256) {
            volatile float* pp = &g_pooled[gg2 * 8];
            float l0 = b0, l1 = b1;
#pragma unroll
            for (int j = 0; j < 8; j++) {
                float p = pp[j];
                l0 = fmaf(p, w0[j], l0);
                l1 = fmaf(p, w1[j], l1);
            }
            float m = fmaxf(l0, l1);
            float lse = m + logf(expf(l0 - m) + expf(l1 - m));
            out[gg2 * 2 + 0] = l0 - lse;
            out[gg2 * 2 + 1] = l1 - lse;
        }
    }
}

// ---------------- launch ----------------
extern "C" void kernel_launch(void* const* d_in, const int* in_sizes, int n_in,
                              void* d_out, int out_size)
{
    const float* x       = (const float*)d_in[0];
    const int*   src     = (const int*)d_in[1];
    const float* w1_pre  = (const float*)d_in[3];
    const float* b1_pre  = (const float*)d_in[4];
    const float* w1_post = (const float*)d_in[5];
    const float* b1_post = (const float*)d_in[6];
    const float* w1_lin  = (const float*)d_in[7];
    const float* b1_lin  = (const float*)d_in[8];
    const float* w2_pre  = (const float*)d_in[9];
    const float* b2_pre  = (const float*)d_in[10];
    const float* w2_post = (const float*)d_in[11];
    const float* b2_post = (const float*)d_in[12];
    const float* w2_lin  = (const float*)d_in[13];
    const float* b2_lin  = (const float*)d_in[14];
    const float* fc_w    = (const float*)d_in[15];
    const float* fc_b    = (const float*)d_in[16];
    float* out = (float*)d_out;

    static int attr_done = 0;
    if (!attr_done) {
        cudaFuncSetAttribute(conv1_kernel, cudaFuncAttributeMaxDynamicSharedMemorySize, 8 * 3 * 512 * 4);
        cudaFuncSetAttribute(conv2_kernel, cudaFuncAttributeMaxDynamicSharedMemorySize, 8 * 3 * 528 * 4);
        attr_done = 1;
    }

    fold_kernel<<<1, 256>>>(w1_pre, b1_pre, w1_post, b1_post, w1_lin, b1_lin);
    ab1_kernel<<<(NN + 127) / 128, 128>>>(x);
    conv1_kernel<<<CGRID1, 256, 8 * 3 * 512 * 4>>>(src, w1_post, w1_lin,
                                                   w2_pre, b2_pre, w2_post, b2_post, w2_lin, b2_lin);
    conv2_kernel<<<CGRID2, 256, 8 * 3 * 528 * 4>>>(src, w2_post, w2_lin, fc_w, fc_b, out);
}

// round 16
// speedup vs baseline: 1.0535x; 1.0535x over previous
#include <cuda_runtime.h>
#include <math.h>

#define NN  200000
#define KK  16
#define GG  4000
#define NPG 50
#define EPS 1e-5f

#define NG1 (NN / 8)
#define NG2 (NN / 16)
#define CGRID1 444      // conv1: 148 SMs * 3 blocks
#define CGRID2 444      // conv2: 148 SMs * 3 blocks

#define CP16(dst, src) asm volatile("cp.async.cg.shared.global [%0], [%1], 16;" :: "r"(dst), "l"(src) : "memory")
#define CP_COMMIT()    asm volatile("cp.async.commit_group;" ::: "memory")
#define CP_WAIT1()     asm volatile("cp.async.wait_group 1;" ::: "memory")
#define CP_WAIT0()     asm volatile("cp.async.wait_group 0;" ::: "memory")

// ---------------- scratch ----------------
__device__ float g_B1[NN * 32];
__device__ float g_D1[NN * 16];
__device__ float g_B2[NN * 16];
__device__ float g_D2[NN * 8];
__device__ float g_pooled[GG * 8];
__device__ unsigned g_ctr = 0;

// folded ab1 weights
__device__ float g_ws1[25 * 28];
__device__ float g_cs1[16 * 28];
__device__ float g_c01[16];

// =================================================================
// kernel 0: one-block fold for ab1's weights
// =================================================================
__global__ void fold_kernel(
    const float* __restrict__ w1_pre, const float* __restrict__ b1_pre,
    const float* __restrict__ w1_post, const float* __restrict__ b1_post,
    const float* __restrict__ w1_lin,  const float* __restrict__ b1_lin)
{
    __shared__ float pa[16 * 25];
    __shared__ float pb[16 * 25];
    int t = threadIdx.x;

    for (int i = t; i < 16 * 25; i += 256) {
        int k = i / 25, jj = i % 25;
        const float* pr = w1_post + k * 300;
        pa[i] = pr[jj] + pr[25 + jj] + pr[50 + jj]
              + pr[100 + jj] + pr[125 + jj] + pr[150 + jj]
              + pr[200 + jj] + pr[225 + jj] + pr[250 + jj];
    }
    __syncthreads();
    for (int i = t; i < 16 * 25; i += 256) {
        int o = i / 25, jj = i % 25;
        float s = 0.f;
        for (int k = 0; k < 16; k++) s = fmaf(w1_lin[o * 16 + k], pa[k * 25 + jj], s);
        pb[i] = s;
    }
    __syncthreads();
    for (int i = t; i < 16 * 28; i += 256) {
        int o = i / 28, ii = i % 28;
        float s = 0.f;
        if (ii < 25) { for (int j = 0; j < 25; j++) s = fmaf(pb[o * 25 + j], w1_pre[j * 50 + ii], s); }
        g_cs1[i] = s;
    }
    for (int i = t; i < 25 * 28; i += 256) {
        int j = i / 28, ii = i % 28;
        g_ws1[i] = (ii < 25) ? w1_pre[j * 50 + 25 + ii] : 0.f;
    }
    if (t < 16) {
        float s = b1_lin[t];
        for (int k = 0; k < 16; k++) s = fmaf(w1_lin[t * 16 + k], b1_post[k], s);
        for (int j = 0; j < 25; j++) s = fmaf(pb[t * 25 + j], b1_pre[j], s);
        g_c01[t] = s;
    }
}

// =================================================================
// kernel 1: ab1 — lean, folded weights from global; zeros g_pooled.
// =================================================================
__global__ void __launch_bounds__(128) ab1_kernel(const float* __restrict__ x)
{
    __shared__ __align__(16) float xs[128 * 28];
    __shared__ __align__(16) float ws[25 * 28];
    __shared__ __align__(16) float cs[16 * 28];
    __shared__ float c0s[16];

    int t = threadIdx.x;
    int base = blockIdx.x * 128;
    int nvalid = NN - base; if (nvalid > 128) nvalid = 128;

    if (blockIdx.x < 250) g_pooled[blockIdx.x * 128 + t] = 0.f;

    for (int i = t; i < 25 * 28; i += 128) ws[i] = g_ws1[i];
    for (int i = t; i < 16 * 28; i += 128) cs[i] = g_cs1[i];
    if (t < 16) c0s[t] = g_c01[t];
    for (int i = t; i < nvalid * 25; i += 128) xs[(i / 25) * 28 + (i % 25)] = x[base * 25 + i];
    for (int i = t; i < nvalid * 3; i += 128) xs[(i / 3) * 28 + 25 + (i % 3)] = 0.f;
    __syncthreads();

    bool act = (t < nvalid);
    float4 xr[7];
    if (act) {
        const float4* xp = (const float4*)&xs[t * 28];
#pragma unroll
        for (int i = 0; i < 7; i++) xr[i] = xp[i];
    }
    __syncthreads();

    if (act) {
        const float4* wp = (const float4*)ws;
#pragma unroll
        for (int j = 0; j < 25; j++) {
            float4 a = make_float4(0.f, 0.f, 0.f, 0.f);
#pragma unroll
            for (int i = 0; i < 7; i++) {
                float4 w4 = wp[j * 7 + i];
                a.x = fmaf(w4.x, xr[i].x, a.x); a.y = fmaf(w4.y, xr[i].y, a.y);
                a.z = fmaf(w4.z, xr[i].z, a.z); a.w = fmaf(w4.w, xr[i].w, a.w);
            }
            xs[t * 28 + j] = (a.x + a.y) + (a.z + a.w);
        }
    }
    __syncthreads();
    for (int i = t; i < nvalid * 32; i += 128) {
        int nd = i >> 5, c = i & 31;
        if (c < 25) g_B1[(base + nd) * 32 + c] = xs[nd * 28 + c];
    }
    __syncthreads();

    if (act) {
        const float4* cp = (const float4*)cs;
#pragma unroll
        for (int o = 0; o < 16; o++) {
            float4 a = make_float4(0.f, 0.f, 0.f, 0.f);
#pragma unroll
            for (int i = 0; i < 7; i++) {
                float4 w4 = cp[o * 7 + i];
                a.x = fmaf(w4.x, xr[i].x, a.x); a.y = fmaf(w4.y, xr[i].y, a.y);
                a.z = fmaf(w4.z, xr[i].z, a.z); a.w = fmaf(w4.w, xr[i].w, a.w);
            }
            xs[t * 16 + o] = c0s[o] + (a.x + a.y) + (a.z + a.w);
        }
    }
    __syncthreads();
    for (int i = t; i < nvalid * 16; i += 128) g_D1[base * 16 + i] = xs[i];
}

// =================================================================
// kernel 2: conv1 — cp.async double-buffered gather (28 floats/edge,
// clean hoisted indexing), W in registers. 3 blocks/SM.
// stats -> matvec -> h1 -> fused ab2 -> B2/D2.
// =================================================================
__global__ void __launch_bounds__(256, 3) conv1_kernel(
    const int* __restrict__ src,
    const float* __restrict__ w1_post, const float* __restrict__ w1_lin,
    const float* __restrict__ w2_pre, const float* __restrict__ b2_pre,
    const float* __restrict__ w2_post, const float* __restrict__ b2_post,
    const float* __restrict__ w2_lin,  const float* __restrict__ b2_lin)
{
    __shared__ __align__(16) float s_stage[8][2][448];   // 28 KB: 16 edges x 28 floats
    __shared__ __align__(16) float s_w1[16 * 108];
    __shared__ __align__(16) float s_agg[8][112];
    __shared__ __align__(16) float4 s_wb[4 * 32];
    __shared__ __align__(16) float s_h1[8][16];
    __shared__ float s_c02[8];

    int t = threadIdx.x;
    float* s_pa  = &s_stage[0][0][0];       // preamble overlay (1984 <= 7168 floats)
    float* s_p92 = s_pa + 1600;
    float* s_wa2 = s_p92 + 128;
    float* s_c2m = s_wa2 + 128;

    for (int i = t; i < 16 * 100; i += 256) {
        int k = i / 100, j = i % 100;
        s_pa[i] = w1_post[k * 300 + j] + w1_post[k * 300 + 100 + j] + w1_post[k * 300 + 200 + j];
    }
    for (int i = t; i < 8 * 16; i += 256) {
        int k = i / 16, jj = i % 16;
        const float* pr = w2_post + k * 192;
        s_p92[i] = pr[jj] + pr[16 + jj] + pr[32 + jj]
                 + pr[64 + jj] + pr[80 + jj] + pr[96 + jj]
                 + pr[128 + jj] + pr[144 + jj] + pr[160 + jj];
    }
    for (int i = t; i < 8 * 112; i += 256) ((float*)s_agg)[i] = 0.f;
    __syncthreads();
    for (int i = t; i < 16 * 108; i += 256) {
        int o = i / 108, j = i % 108;
        float s = 0.f;
        if (j < 100) { for (int k = 0; k < 16; k++) s = fmaf(w1_lin[o * 16 + k], s_pa[k * 100 + j], s); }
        s_w1[i] = s;
    }
    for (int i = t; i < 8 * 16; i += 256) {
        int o = i / 16, jj = i % 16;
        float s = 0.f;
        for (int k = 0; k < 8; k++) s = fmaf(w2_lin[o * 8 + k], s_p92[k * 16 + jj], s);
        s_wa2[i] = s;
    }
    __syncthreads();
    for (int i = t; i < 8 * 16; i += 256) {
        int o = i / 16, ii = i % 16;
        float s = 0.f;
        for (int j = 0; j < 16; j++) s = fmaf(s_wa2[o * 16 + j], w2_pre[j * 32 + ii], s);
        s_c2m[i] = s;
    }
    if (t < 8) {
        float s = b2_lin[t];
        for (int k = 0; k < 8; k++) s = fmaf(w2_lin[t * 8 + k], b2_post[k], s);
        for (int j = 0; j < 16; j++) s = fmaf(s_wa2[t * 16 + j], b2_pre[j], s);
        s_c02[t] = s;
    }
    __syncthreads();
    for (int i = t; i < 4 * 32; i += 256) {
        int i4 = i / 32, l = i % 32;
        float4 v = make_float4(0.f, 0.f, 0.f, 0.f);
        if (l < 16) {
            v.x = w2_pre[l * 32 + 16 + i4 * 4 + 0];
            v.y = w2_pre[l * 32 + 16 + i4 * 4 + 1];
            v.z = w2_pre[l * 32 + 16 + i4 * 4 + 2];
            v.w = w2_pre[l * 32 + 16 + i4 * 4 + 3];
        } else if (l < 24) {
            int o = l - 16;
            v.x = s_c2m[o * 16 + i4 * 4 + 0];
            v.y = s_c2m[o * 16 + i4 * 4 + 1];
            v.z = s_c2m[o * 16 + i4 * 4 + 2];
            v.w = s_c2m[o * 16 + i4 * 4 + 3];
        }
        s_wb[i] = v;
    }
    __syncthreads();   // stage free after this point

    int w = t >> 5, lane = t & 31;
    int o = lane & 15, hf = lane >> 4;
    int el = lane / 7;            // edge sub-index for gather (0..4)
    int ck = lane % 7;            // chunk-in-edge (0..6)
    bool gact = (lane < 28);

    float4 Wr[13];
    {
        const float4* wrow = (const float4*)&s_w1[o * 108 + hf * 52];
#pragma unroll
        for (int j = 0; j < 13; j++) Wr[j] = wrow[j];
    }

    unsigned stg0 = (unsigned)__cvta_generic_to_shared(&s_stage[w][0][0]) + lane * 16;
    unsigned stg1 = (unsigned)__cvta_generic_to_shared(&s_stage[w][1][0]) + lane * 16;
    int ckoff = ck * 4;

    int grp = blockIdx.x;
    {
        int sv_c = __ldg(&src[(grp * 8 + w) * 16 + (lane & 15)]);
#pragma unroll
        for (int ph = 0; ph < 4; ph++) {
            int s = __shfl_sync(0xffffffffu, sv_c, (4 * ph + el) & 15);
            if (gact) CP16(stg0 + ph * 448, &g_B1[s * 32 + ckoff]);
        }
        CP_COMMIT();
    }
    float d1_c = (lane < 16) ? __ldg(&g_D1[(grp * 8 + w) * 16 + lane]) : 0.f;
    int grp_n = grp + CGRID1;
    int sv_n = 0; float d1_n = 0.f;
    if (grp_n < NG1) {
        sv_n = __ldg(&src[(grp_n * 8 + w) * 16 + (lane & 15)]);
        if (lane < 16) d1_n = __ldg(&g_D1[(grp_n * 8 + w) * 16 + lane]);
    }

    int buf = 0;
    while (true) {
        bool has_next = (grp_n < NG1);
        if (has_next) {
            unsigned dstb = buf ? stg0 : stg1;
#pragma unroll
            for (int ph = 0; ph < 4; ph++) {
                int s = __shfl_sync(0xffffffffu, sv_n, (4 * ph + el) & 15);
                if (gact) CP16(dstb + ph * 448, &g_B1[s * 32 + ckoff]);
            }
            CP_COMMIT();
        }
        int grp_nn = grp_n + CGRID1;
        int sv_nn = 0; float d1_nn = 0.f;
        if (has_next && grp_nn < NG1) {
            sv_nn = __ldg(&src[(grp_nn * 8 + w) * 16 + (lane & 15)]);
            if (lane < 16) d1_nn = __ldg(&g_D1[(grp_nn * 8 + w) * 16 + lane]);
        }
        if (has_next) CP_WAIT1(); else CP_WAIT0();
        __syncwarp();

        const float* sg = &s_stage[w][buf][0];
        if (lane < 25) {
            float sa = 0.f, sb = 0.f, qa = 0.f, qb = 0.f;
            float mna = 1e30f, mnb = 1e30f, mxa = -1e30f, mxb = -1e30f;
#pragma unroll
            for (int e = 0; e < 16; e += 2) {
                float a = sg[e * 28 + lane];
                float bq = sg[(e + 1) * 28 + lane];
                sa += a;  qa = fmaf(a, a, qa);  mna = fminf(mna, a);  mxa = fmaxf(mxa, a);
                sb += bq; qb = fmaf(bq, bq, qb); mnb = fminf(mnb, bq); mxb = fmaxf(mxb, bq);
            }
            float sum = sa + sb, sq = qa + qb;
            float mn = fminf(mna, mnb), mx = fmaxf(mxa, mxb);
            float mean = sum * (1.f / 16.f), m2 = sq * (1.f / 16.f);
            float st = sqrtf(fmaxf(m2 - mean * mean, 0.f) + EPS);
            s_agg[w][lane]      = mean;
            s_agg[w][25 + lane] = mn;
            s_agg[w][50 + lane] = mx;
            s_agg[w][75 + lane] = st;
        }
        __syncwarp();
        int n = grp * 8 + w;
        {
            const float4* ar = (const float4*)&s_agg[w][hf * 52];
            float4 a4 = make_float4(0.f, 0.f, 0.f, 0.f);
#pragma unroll
            for (int j = 0; j < 13; j++) {
                float4 av = ar[j];
                a4.x = fmaf(Wr[j].x, av.x, a4.x); a4.y = fmaf(Wr[j].y, av.y, a4.y);
                a4.z = fmaf(Wr[j].z, av.z, a4.z); a4.w = fmaf(Wr[j].w, av.w, a4.w);
            }
            float p = (a4.x + a4.y) + (a4.z + a4.w);
            p += __shfl_xor_sync(0xffffffffu, p, 16);
            if (lane < 16) s_h1[w][lane] = fmaxf(p + d1_c, 0.f);
        }
        __syncwarp();
        {
            float acc = (lane >= 16 && lane < 24) ? s_c02[lane - 16] : 0.f;
            const float4* h4 = (const float4*)&s_h1[w][0];
#pragma unroll
            for (int i4 = 0; i4 < 4; i4++) {
                float4 hv = h4[i4];
                float4 wv = s_wb[i4 * 32 + lane];
                acc = fmaf(wv.x, hv.x, acc); acc = fmaf(wv.y, hv.y, acc);
                acc = fmaf(wv.z, hv.z, acc); acc = fmaf(wv.w, hv.w, acc);
            }
            if (lane < 16)      g_B2[n * 16 + lane] = acc;
            else if (lane < 24) g_D2[n * 8 + lane - 16] = acc;
        }
        __syncwarp();

        if (!has_next) break;
        grp = grp_n; grp_n = grp_nn;
        d1_c = d1_n; d1_n = d1_nn; sv_n = sv_nn;
        buf ^= 1;
    }
}

// =================================================================
// kernel 3: conv2 — exact R13: cp.async gather + W in registers,
// 3 blocks/SM; fused pooling + final FC.
// =================================================================
__global__ void __launch_bounds__(256, 3) conv2_kernel(
    const int* __restrict__ src,
    const float* __restrict__ w2_post, const float* __restrict__ w2_lin,
    const float* __restrict__ fc_w, const float* __restrict__ fc_b,
    float* __restrict__ out)
{
    __shared__ __align__(16) float s_stage[8][2][528];
    __shared__ __align__(16) float s_w2[8 * 72];
    __shared__ __align__(16) float s_agg[8][2][72];
    __shared__ unsigned s_rank;

    int t = threadIdx.x;
    float* s_pa = &s_stage[0][0][0];

    for (int i = t; i < 8 * 64; i += 256) {
        int k = i / 64, j = i % 64;
        s_pa[i] = w2_post[k * 192 + j] + w2_post[k * 192 + 64 + j] + w2_post[k * 192 + 128 + j];
    }
    for (int i = t; i < 8 * 72; i += 256) s_w2[i] = 0.f;
    for (int i = t; i < 8 * 2 * 72; i += 256) ((float*)s_agg)[i] = 0.f;
    __syncthreads();
    for (int i = t; i < 8 * 64; i += 256) {
        int o = i / 64, j = i % 64;
        float s = 0.f;
        for (int k = 0; k < 8; k++) s = fmaf(w2_lin[o * 8 + k], s_pa[k * 64 + j], s);
        int bq = j >> 4, r = j & 15;
        const int off[4] = {0, 16, 36, 52};
        s_w2[o * 72 + off[bq] + r] = s;
    }
    __syncthreads();

    int w = t >> 5, lane = t & 31;
    int node = lane >> 4, r = lane & 15;
    int o = r >> 1, hf = r & 1;

    float4 Wr[8];
    {
        const float4* wrow = (const float4*)&s_w2[o * 72 + hf * 36];
#pragma unroll
        for (int j = 0; j < 8; j++) Wr[j] = wrow[j];
    }

    unsigned stg0 = (unsigned)__cvta_generic_to_shared(&s_stage[w][0][0]);
    unsigned stg1 = (unsigned)__cvta_generic_to_shared(&s_stage[w][1][0]);

    int grp = blockIdx.x;
    {
        int sv_c = __ldg(&src[(grp * 8 + w) * 32 + lane]);
#pragma unroll
        for (int ph = 0; ph < 4; ph++) {
            int c = ph * 32 + lane;
            int e = c >> 2;
            int s = __shfl_sync(0xffffffffu, sv_c, e);
            int row = (e < 16) ? e : (e + 1);
            CP16(stg0 + row * 64 + (c & 3) * 16, &g_B2[s * 16 + (c & 3) * 4]);
        }
        CP_COMMIT();
    }
    float d2_c = (hf == 0) ? __ldg(&g_D2[((grp * 8 + w) * 2 + node) * 8 + o]) : 0.f;
    int grp_n = grp + CGRID2;
    int sv_n = 0; float d2_n = 0.f;
    if (grp_n < NG2) {
        sv_n = __ldg(&src[(grp_n * 8 + w) * 32 + lane]);
        if (hf == 0) d2_n = __ldg(&g_D2[((grp_n * 8 + w) * 2 + node) * 8 + o]);
    }

    int buf = 0;
    while (true) {
        bool has_next = (grp_n < NG2);
        if (has_next) {
            unsigned dstb = buf ? stg0 : stg1;
#pragma unroll
            for (int ph = 0; ph < 4; ph++) {
                int c = ph * 32 + lane;
                int e = c >> 2;
                int s = __shfl_sync(0xffffffffu, sv_n, e);
                int row = (e < 16) ? e : (e + 1);
                CP16(dstb + row * 64 + (c & 3) * 16, &g_B2[s * 16 + (c & 3) * 4]);
            }
            CP_COMMIT();
        }
        int grp_nn = grp_n + CGRID2;
        int sv_nn = 0; float d2_nn = 0.f;
        if (has_next && grp_nn < NG2) {
            sv_nn = __ldg(&src[(grp_nn * 8 + w) * 32 + lane]);
            if (hf == 0) d2_nn = __ldg(&g_D2[((grp_nn * 8 + w) * 2 + node) * 8 + o]);
        }
        if (has_next) CP_WAIT1(); else CP_WAIT0();
        __syncwarp();

        const float* sg = &s_stage[w][buf][0];
        {
            int f = lane & 15;
            int rb = (lane >> 4) ? 17 : 0;
            float sa = 0.f, sb = 0.f, qa = 0.f, qb = 0.f;
            float mna = 1e30f, mnb = 1e30f, mxa = -1e30f, mxb = -1e30f;
#pragma unroll
            for (int e = 0; e < 16; e += 2) {
                float a = sg[(rb + e) * 16 + f];
                float bq = sg[(rb + e + 1) * 16 + f];
                sa += a;  qa = fmaf(a, a, qa);  mna = fminf(mna, a);  mxa = fmaxf(mxa, a);
                sb += bq; qb = fmaf(bq, bq, qb); mnb = fminf(mnb, bq); mxb = fmaxf(mxb, bq);
            }
            float sum = sa + sb, sq = qa + qb;
            float mn = fminf(mna, mnb), mx = fmaxf(mxa, mxb);
            float mean = sum * (1.f / 16.f), m2 = sq * (1.f / 16.f);
            float st = sqrtf(fmaxf(m2 - mean * mean, 0.f) + EPS);
            int nd = lane >> 4;
            s_agg[w][nd][f]      = mean;
            s_agg[w][nd][16 + f] = mn;
            s_agg[w][nd][36 + f] = mx;
            s_agg[w][nd][52 + f] = st;
        }
        __syncwarp();
        int nA = (grp * 8 + w) * 2;
        {
            const float4* ar = (const float4*)&s_agg[w][node][hf * 36];
            float4 a4 = make_float4(0.f, 0.f, 0.f, 0.f);
#pragma unroll
            for (int j = 0; j < 8; j++) {
                float4 av = ar[j];
                a4.x = fmaf(Wr[j].x, av.x, a4.x); a4.y = fmaf(Wr[j].y, av.y, a4.y);
                a4.z = fmaf(Wr[j].z, av.z, a4.z); a4.w = fmaf(Wr[j].w, av.w, a4.w);
            }
            float p = (a4.x + a4.y) + (a4.z + a4.w);
            p += __shfl_xor_sync(0xffffffffu, p, 1);
            if (hf == 0) {
                float h = fmaxf(p + d2_c, 0.f);
                atomicAdd(&g_pooled[((nA + node) / NPG) * 8 + o], h);
            }
        }
        __syncwarp();

        if (!has_next) break;
        grp = grp_n; grp_n = grp_nn;
        d2_c = d2_n; d2_n = d2_nn; sv_n = sv_nn;
        buf ^= 1;
    }

    // ---- fused final: last block computes FC + log_softmax ----
    __syncthreads();
    __threadfence();
    if (t == 0) s_rank = atomicAdd(&g_ctr, 1u);
    __syncthreads();
    if (s_rank == (unsigned)(gridDim.x - 1)) {
        if (t == 0) g_ctr = 0;
        float w0[8], w1[8];
#pragma unroll
        for (int j = 0; j < 8; j++) { w0[j] = fc_w[j]; w1[j] = fc_w[8 + j]; }
        float b0 = fc_b[0], b1 = fc_b[1];
        for (int g = t; g < GG; g += 256) {
            volatile float* pp = &g_pooled[g * 8];
            float l0 = b0, l1 = b1;
#pragma unroll
            for (int j = 0; j < 8; j++) {
                float p = pp[j];
                l0 = fmaf(p, w0[j], l0);
                l1 = fmaf(p, w1[j], l1);
            }
            float m = fmaxf(l0, l1);
            float lse = m + logf(expf(l0 - m) + expf(l1 - m));
            out[g * 2 + 0] = l0 - lse;
            out[g * 2 + 1] = l1 - lse;
        }
    }
}

// ---------------- launch ----------------
extern "C" void kernel_launch(void* const* d_in, const int* in_sizes, int n_in,
                              void* d_out, int out_size)
{
    const float* x       = (const float*)d_in[0];
    const int*   src     = (const int*)d_in[1];
    const float* w1_pre  = (const float*)d_in[3];
    const float* b1_pre  = (const float*)d_in[4];
    const float* w1_post = (const float*)d_in[5];
    const float* b1_post = (const float*)d_in[6];
    const float* w1_lin  = (const float*)d_in[7];
    const float* b1_lin  = (const float*)d_in[8];
    const float* w2_pre  = (const float*)d_in[9];
    const float* b2_pre  = (const float*)d_in[10];
    const float* w2_post = (const float*)d_in[11];
    const float* b2_post = (const float*)d_in[12];
    const float* w2_lin  = (const float*)d_in[13];
    const float* b2_lin  = (const float*)d_in[14];
    const float* fc_w    = (const float*)d_in[15];
    const float* fc_b    = (const float*)d_in[16];
    float* out = (float*)d_out;

    fold_kernel<<<1, 256>>>(w1_pre, b1_pre, w1_post, b1_post, w1_lin, b1_lin);
    ab1_kernel<<<(NN + 127) / 128, 128>>>(x);
    conv1_kernel<<<CGRID1, 256>>>(src, w1_post, w1_lin,
                                  w2_pre, b2_pre, w2_post, b2_post, w2_lin, b2_lin);
    conv2_kernel<<<CGRID2, 256>>>(src, w2_post, w2_lin, fc_w, fc_b, out);
}

// round 17
// speedup vs baseline: 1.0972x; 1.0415x over previous
#include <cuda_runtime.h>
#include <math.h>

#define NN  200000
#define KK  16
#define GG  4000
#define NPG 50
#define EPS 1e-5f

#define NG1 (NN / 8)
#define NG2 (NN / 16)
#define CGRID1 444      // conv1: 148 SMs * 3 blocks
#define CGRID2 444      // conv2: 148 SMs * 3 blocks

#define CP16(dst, src) asm volatile("cp.async.cg.shared.global [%0], [%1], 16;" :: "r"(dst), "l"(src) : "memory")
#define CP_COMMIT()    asm volatile("cp.async.commit_group;" ::: "memory")
#define CP_WAIT1()     asm volatile("cp.async.wait_group 1;" ::: "memory")
#define CP_WAIT0()     asm volatile("cp.async.wait_group 0;" ::: "memory")

// ---------------- scratch ----------------
__device__ float g_B1[NN * 32];
__device__ float g_D1[NN * 16];
__device__ float g_B2[NN * 16];
__device__ float g_D2[NN * 8];
__device__ float g_pooled[GG * 8];
__device__ unsigned g_ctr = 0;

// folded ab1 weights
__device__ float g_ws1[25 * 28];
__device__ float g_cs1[16 * 28];
__device__ float g_c01[16];

// =================================================================
// kernel 0: one-block fold for ab1's weights
// =================================================================
__global__ void fold_kernel(
    const float* __restrict__ w1_pre, const float* __restrict__ b1_pre,
    const float* __restrict__ w1_post, const float* __restrict__ b1_post,
    const float* __restrict__ w1_lin,  const float* __restrict__ b1_lin)
{
    __shared__ float pa[16 * 25];
    __shared__ float pb[16 * 25];
    int t = threadIdx.x;

    for (int i = t; i < 16 * 25; i += 256) {
        int k = i / 25, jj = i % 25;
        const float* pr = w1_post + k * 300;
        pa[i] = pr[jj] + pr[25 + jj] + pr[50 + jj]
              + pr[100 + jj] + pr[125 + jj] + pr[150 + jj]
              + pr[200 + jj] + pr[225 + jj] + pr[250 + jj];
    }
    __syncthreads();
    for (int i = t; i < 16 * 25; i += 256) {
        int o = i / 25, jj = i % 25;
        float s = 0.f;
        for (int k = 0; k < 16; k++) s = fmaf(w1_lin[o * 16 + k], pa[k * 25 + jj], s);
        pb[i] = s;
    }
    __syncthreads();
    for (int i = t; i < 16 * 28; i += 256) {
        int o = i / 28, ii = i % 28;
        float s = 0.f;
        if (ii < 25) { for (int j = 0; j < 25; j++) s = fmaf(pb[o * 25 + j], w1_pre[j * 50 + ii], s); }
        g_cs1[i] = s;
    }
    for (int i = t; i < 25 * 28; i += 256) {
        int j = i / 28, ii = i % 28;
        g_ws1[i] = (ii < 25) ? w1_pre[j * 50 + 25 + ii] : 0.f;
    }
    if (t < 16) {
        float s = b1_lin[t];
        for (int k = 0; k < 16; k++) s = fmaf(w1_lin[t * 16 + k], b1_post[k], s);
        for (int j = 0; j < 25; j++) s = fmaf(pb[t * 25 + j], b1_pre[j], s);
        g_c01[t] = s;
    }
}

// =================================================================
// kernel 1: ab1 — 256 threads/block (halved preamble replication);
// lean per-node path identical to R13.
// =================================================================
__global__ void __launch_bounds__(256) ab1_kernel(const float* __restrict__ x)
{
    __shared__ __align__(16) float xs[256 * 28];
    __shared__ __align__(16) float ws[25 * 28];
    __shared__ __align__(16) float cs[16 * 28];
    __shared__ float c0s[16];

    int t = threadIdx.x;
    int base = blockIdx.x * 256;
    int nvalid = NN - base; if (nvalid > 256) nvalid = 256;

    if (blockIdx.x < 125) g_pooled[blockIdx.x * 256 + t] = 0.f;

    for (int i = t; i < 25 * 28; i += 256) ws[i] = g_ws1[i];
    for (int i = t; i < 16 * 28; i += 256) cs[i] = g_cs1[i];
    if (t < 16) c0s[t] = g_c01[t];
    for (int i = t; i < nvalid * 25; i += 256) xs[(i / 25) * 28 + (i % 25)] = x[base * 25 + i];
    for (int i = t; i < nvalid * 3; i += 256) xs[(i / 3) * 28 + 25 + (i % 3)] = 0.f;
    __syncthreads();

    bool act = (t < nvalid);
    float4 xr[7];
    if (act) {
        const float4* xp = (const float4*)&xs[t * 28];
#pragma unroll
        for (int i = 0; i < 7; i++) xr[i] = xp[i];
    }
    __syncthreads();

    if (act) {
        const float4* wp = (const float4*)ws;
#pragma unroll
        for (int j = 0; j < 25; j++) {
            float4 a = make_float4(0.f, 0.f, 0.f, 0.f);
#pragma unroll
            for (int i = 0; i < 7; i++) {
                float4 w4 = wp[j * 7 + i];
                a.x = fmaf(w4.x, xr[i].x, a.x); a.y = fmaf(w4.y, xr[i].y, a.y);
                a.z = fmaf(w4.z, xr[i].z, a.z); a.w = fmaf(w4.w, xr[i].w, a.w);
            }
            xs[t * 28 + j] = (a.x + a.y) + (a.z + a.w);
        }
    }
    __syncthreads();
    for (int i = t; i < nvalid * 32; i += 256) {
        int nd = i >> 5, c = i & 31;
        if (c < 25) g_B1[(base + nd) * 32 + c] = xs[nd * 28 + c];
    }
    __syncthreads();

    if (act) {
        const float4* cp = (const float4*)cs;
#pragma unroll
        for (int o = 0; o < 16; o++) {
            float4 a = make_float4(0.f, 0.f, 0.f, 0.f);
#pragma unroll
            for (int i = 0; i < 7; i++) {
                float4 w4 = cp[o * 7 + i];
                a.x = fmaf(w4.x, xr[i].x, a.x); a.y = fmaf(w4.y, xr[i].y, a.y);
                a.z = fmaf(w4.z, xr[i].z, a.z); a.w = fmaf(w4.w, xr[i].w, a.w);
            }
            xs[t * 16 + o] = c0s[o] + (a.x + a.y) + (a.z + a.w);
        }
    }
    __syncthreads();
    for (int i = t; i < nvalid * 16; i += 256) g_D1[base * 16 + i] = xs[i];
}

// =================================================================
// kernel 2: conv1 — exact R13: cp.async double-buffered gather
// (32 floats/edge, c>>3 addressing), W in registers, 3 blocks/SM.
// =================================================================
__global__ void __launch_bounds__(256, 3) conv1_kernel(
    const int* __restrict__ src,
    const float* __restrict__ w1_post, const float* __restrict__ w1_lin,
    const float* __restrict__ w2_pre, const float* __restrict__ b2_pre,
    const float* __restrict__ w2_post, const float* __restrict__ b2_post,
    const float* __restrict__ w2_lin,  const float* __restrict__ b2_lin)
{
    __shared__ __align__(16) float s_stage[8][2][512];
    __shared__ __align__(16) float s_w1[16 * 108];
    __shared__ __align__(16) float s_agg[8][112];
    __shared__ __align__(16) float4 s_wb[4 * 32];
    __shared__ __align__(16) float s_h1[8][16];
    __shared__ float s_c02[8];

    int t = threadIdx.x;
    float* s_pa  = &s_stage[0][0][0];
    float* s_p92 = s_pa + 1600;
    float* s_wa2 = s_p92 + 128;
    float* s_c2m = s_wa2 + 128;

    for (int i = t; i < 16 * 100; i += 256) {
        int k = i / 100, j = i % 100;
        s_pa[i] = w1_post[k * 300 + j] + w1_post[k * 300 + 100 + j] + w1_post[k * 300 + 200 + j];
    }
    for (int i = t; i < 8 * 16; i += 256) {
        int k = i / 16, jj = i % 16;
        const float* pr = w2_post + k * 192;
        s_p92[i] = pr[jj] + pr[16 + jj] + pr[32 + jj]
                 + pr[64 + jj] + pr[80 + jj] + pr[96 + jj]
                 + pr[128 + jj] + pr[144 + jj] + pr[160 + jj];
    }
    for (int i = t; i < 8 * 112; i += 256) ((float*)s_agg)[i] = 0.f;
    __syncthreads();
    for (int i = t; i < 16 * 108; i += 256) {
        int o = i / 108, j = i % 108;
        float s = 0.f;
        if (j < 100) { for (int k = 0; k < 16; k++) s = fmaf(w1_lin[o * 16 + k], s_pa[k * 100 + j], s); }
        s_w1[i] = s;
    }
    for (int i = t; i < 8 * 16; i += 256) {
        int o = i / 16, jj = i % 16;
        float s = 0.f;
        for (int k = 0; k < 8; k++) s = fmaf(w2_lin[o * 8 + k], s_p92[k * 16 + jj], s);
        s_wa2[i] = s;
    }
    __syncthreads();
    for (int i = t; i < 8 * 16; i += 256) {
        int o = i / 16, ii = i % 16;
        float s = 0.f;
        for (int j = 0; j < 16; j++) s = fmaf(s_wa2[o * 16 + j], w2_pre[j * 32 + ii], s);
        s_c2m[i] = s;
    }
    if (t < 8) {
        float s = b2_lin[t];
        for (int k = 0; k < 8; k++) s = fmaf(w2_lin[t * 8 + k], b2_post[k], s);
        for (int j = 0; j < 16; j++) s = fmaf(s_wa2[t * 16 + j], b2_pre[j], s);
        s_c02[t] = s;
    }
    __syncthreads();
    for (int i = t; i < 4 * 32; i += 256) {
        int i4 = i / 32, l = i % 32;
        float4 v = make_float4(0.f, 0.f, 0.f, 0.f);
        if (l < 16) {
            v.x = w2_pre[l * 32 + 16 + i4 * 4 + 0];
            v.y = w2_pre[l * 32 + 16 + i4 * 4 + 1];
            v.z = w2_pre[l * 32 + 16 + i4 * 4 + 2];
            v.w = w2_pre[l * 32 + 16 + i4 * 4 + 3];
        } else if (l < 24) {
            int o = l - 16;
            v.x = s_c2m[o * 16 + i4 * 4 + 0];
            v.y = s_c2m[o * 16 + i4 * 4 + 1];
            v.z = s_c2m[o * 16 + i4 * 4 + 2];
            v.w = s_c2m[o * 16 + i4 * 4 + 3];
        }
        s_wb[i] = v;
    }
    __syncthreads();

    int w = t >> 5, lane = t & 31;
    int o = lane & 15, hf = lane >> 4;

    float4 Wr[13];
    {
        const float4* wrow = (const float4*)&s_w1[o * 108 + hf * 52];
#pragma unroll
        for (int j = 0; j < 13; j++) Wr[j] = wrow[j];
    }

    unsigned stg0 = (unsigned)__cvta_generic_to_shared(&s_stage[w][0][0]);
    unsigned stg1 = (unsigned)__cvta_generic_to_shared(&s_stage[w][1][0]);

    int grp = blockIdx.x;
    {
        int sv_c = __ldg(&src[(grp * 8 + w) * 16 + (lane & 15)]);
#pragma unroll
        for (int ph = 0; ph < 4; ph++) {
            int c = ph * 32 + lane;
            int s = __shfl_sync(0xffffffffu, sv_c, c >> 3);
            CP16(stg0 + c * 16, &g_B1[s * 32 + (c & 7) * 4]);
        }
        CP_COMMIT();
    }
    float d1_c = (lane < 16) ? __ldg(&g_D1[(grp * 8 + w) * 16 + lane]) : 0.f;
    int grp_n = grp + CGRID1;
    int sv_n = 0; float d1_n = 0.f;
    if (grp_n < NG1) {
        sv_n = __ldg(&src[(grp_n * 8 + w) * 16 + (lane & 15)]);
        if (lane < 16) d1_n = __ldg(&g_D1[(grp_n * 8 + w) * 16 + lane]);
    }

    int buf = 0;
    while (true) {
        bool has_next = (grp_n < NG1);
        if (has_next) {
            unsigned dstb = buf ? stg0 : stg1;
#pragma unroll
            for (int ph = 0; ph < 4; ph++) {
                int c = ph * 32 + lane;
                int s = __shfl_sync(0xffffffffu, sv_n, c >> 3);
                CP16(dstb + c * 16, &g_B1[s * 32 + (c & 7) * 4]);
            }
            CP_COMMIT();
        }
        int grp_nn = grp_n + CGRID1;
        int sv_nn = 0; float d1_nn = 0.f;
        if (has_next && grp_nn < NG1) {
            sv_nn = __ldg(&src[(grp_nn * 8 + w) * 16 + (lane & 15)]);
            if (lane < 16) d1_nn = __ldg(&g_D1[(grp_nn * 8 + w) * 16 + lane]);
        }
        if (has_next) CP_WAIT1(); else CP_WAIT0();
        __syncwarp();

        const float* sg = &s_stage[w][buf][0];
        if (lane < 25) {
            float sa = 0.f, sb = 0.f, qa = 0.f, qb = 0.f;
            float mna = 1e30f, mnb = 1e30f, mxa = -1e30f, mxb = -1e30f;
#pragma unroll
            for (int e = 0; e < 16; e += 2) {
                float a = sg[e * 32 + lane];
                float bq = sg[(e + 1) * 32 + lane];
                sa += a;  qa = fmaf(a, a, qa);  mna = fminf(mna, a);  mxa = fmaxf(mxa, a);
                sb += bq; qb = fmaf(bq, bq, qb); mnb = fminf(mnb, bq); mxb = fmaxf(mxb, bq);
            }
            float sum = sa + sb, sq = qa + qb;
            float mn = fminf(mna, mnb), mx = fmaxf(mxa, mxb);
            float mean = sum * (1.f / 16.f), m2 = sq * (1.f / 16.f);
            float st = sqrtf(fmaxf(m2 - mean * mean, 0.f) + EPS);
            s_agg[w][lane]      = mean;
            s_agg[w][25 + lane] = mn;
            s_agg[w][50 + lane] = mx;
            s_agg[w][75 + lane] = st;
        }
        __syncwarp();
        int n = grp * 8 + w;
        {
            const float4* ar = (const float4*)&s_agg[w][hf * 52];
            float4 a4 = make_float4(0.f, 0.f, 0.f, 0.f);
#pragma unroll
            for (int j = 0; j < 13; j++) {
                float4 av = ar[j];
                a4.x = fmaf(Wr[j].x, av.x, a4.x); a4.y = fmaf(Wr[j].y, av.y, a4.y);
                a4.z = fmaf(Wr[j].z, av.z, a4.z); a4.w = fmaf(Wr[j].w, av.w, a4.w);
            }
            float p = (a4.x + a4.y) + (a4.z + a4.w);
            p += __shfl_xor_sync(0xffffffffu, p, 16);
            if (lane < 16) s_h1[w][lane] = fmaxf(p + d1_c, 0.f);
        }
        __syncwarp();
        {
            float acc = (lane >= 16 && lane < 24) ? s_c02[lane - 16] : 0.f;
            const float4* h4 = (const float4*)&s_h1[w][0];
#pragma unroll
            for (int i4 = 0; i4 < 4; i4++) {
                float4 hv = h4[i4];
                float4 wv = s_wb[i4 * 32 + lane];
                acc = fmaf(wv.x, hv.x, acc); acc = fmaf(wv.y, hv.y, acc);
                acc = fmaf(wv.z, hv.z, acc); acc = fmaf(wv.w, hv.w, acc);
            }
            if (lane < 16)      g_B2[n * 16 + lane] = acc;
            else if (lane < 24) g_D2[n * 8 + lane - 16] = acc;
        }
        __syncwarp();

        if (!has_next) break;
        grp = grp_n; grp_n = grp_nn;
        d1_c = d1_n; d1_n = d1_nn; sv_n = sv_nn;
        buf ^= 1;
    }
}

// =================================================================
// kernel 3: conv2 — exact R13: cp.async gather + W in registers,
// 3 blocks/SM; fused pooling + final FC.
// =================================================================
__global__ void __launch_bounds__(256, 3) conv2_kernel(
    const int* __restrict__ src,
    const float* __restrict__ w2_post, const float* __restrict__ w2_lin,
    const float* __restrict__ fc_w, const float* __restrict__ fc_b,
    float* __restrict__ out)
{
    __shared__ __align__(16) float s_stage[8][2][528];
    __shared__ __align__(16) float s_w2[8 * 72];
    __shared__ __align__(16) float s_agg[8][2][72];
    __shared__ unsigned s_rank;

    int t = threadIdx.x;
    float* s_pa = &s_stage[0][0][0];

    for (int i = t; i < 8 * 64; i += 256) {
        int k = i / 64, j = i % 64;
        s_pa[i] = w2_post[k * 192 + j] + w2_post[k * 192 + 64 + j] + w2_post[k * 192 + 128 + j];
    }
    for (int i = t; i < 8 * 72; i += 256) s_w2[i] = 0.f;
    for (int i = t; i < 8 * 2 * 72; i += 256) ((float*)s_agg)[i] = 0.f;
    __syncthreads();
    for (int i = t; i < 8 * 64; i += 256) {
        int o = i / 64, j = i % 64;
        float s = 0.f;
        for (int k = 0; k < 8; k++) s = fmaf(w2_lin[o * 8 + k], s_pa[k * 64 + j], s);
        int bq = j >> 4, r = j & 15;
        const int off[4] = {0, 16, 36, 52};
        s_w2[o * 72 + off[bq] + r] = s;
    }
    __syncthreads();

    int w = t >> 5, lane = t & 31;
    int node = lane >> 4, r = lane & 15;
    int o = r >> 1, hf = r & 1;

    float4 Wr[8];
    {
        const float4* wrow = (const float4*)&s_w2[o * 72 + hf * 36];
#pragma unroll
        for (int j = 0; j < 8; j++) Wr[j] = wrow[j];
    }

    unsigned stg0 = (unsigned)__cvta_generic_to_shared(&s_stage[w][0][0]);
    unsigned stg1 = (unsigned)__cvta_generic_to_shared(&s_stage[w][1][0]);

    int grp = blockIdx.x;
    {
        int sv_c = __ldg(&src[(grp * 8 + w) * 32 + lane]);
#pragma unroll
        for (int ph = 0; ph < 4; ph++) {
            int c = ph * 32 + lane;
            int e = c >> 2;
            int s = __shfl_sync(0xffffffffu, sv_c, e);
            int row = (e < 16) ? e : (e + 1);
            CP16(stg0 + row * 64 + (c & 3) * 16, &g_B2[s * 16 + (c & 3) * 4]);
        }
        CP_COMMIT();
    }
    float d2_c = (hf == 0) ? __ldg(&g_D2[((grp * 8 + w) * 2 + node) * 8 + o]) : 0.f;
    int grp_n = grp + CGRID2;
    int sv_n = 0; float d2_n = 0.f;
    if (grp_n < NG2) {
        sv_n = __ldg(&src[(grp_n * 8 + w) * 32 + lane]);
        if (hf == 0) d2_n = __ldg(&g_D2[((grp_n * 8 + w) * 2 + node) * 8 + o]);
    }

    int buf = 0;
    while (true) {
        bool has_next = (grp_n < NG2);
        if (has_next) {
            unsigned dstb = buf ? stg0 : stg1;
#pragma unroll
            for (int ph = 0; ph < 4; ph++) {
                int c = ph * 32 + lane;
                int e = c >> 2;
                int s = __shfl_sync(0xffffffffu, sv_n, e);
                int row = (e < 16) ? e : (e + 1);
                CP16(dstb + row * 64 + (c & 3) * 16, &g_B2[s * 16 + (c & 3) * 4]);
            }
            CP_COMMIT();
        }
        int grp_nn = grp_n + CGRID2;
        int sv_nn = 0; float d2_nn = 0.f;
        if (has_next && grp_nn < NG2) {
            sv_nn = __ldg(&src[(grp_nn * 8 + w) * 32 + lane]);
            if (hf == 0) d2_nn = __ldg(&g_D2[((grp_nn * 8 + w) * 2 + node) * 8 + o]);
        }
        if (has_next) CP_WAIT1(); else CP_WAIT0();
        __syncwarp();

        const float* sg = &s_stage[w][buf][0];
        {
            int f = lane & 15;
            int rb = (lane >> 4) ? 17 : 0;
            float sa = 0.f, sb = 0.f, qa = 0.f, qb = 0.f;
            float mna = 1e30f, mnb = 1e30f, mxa = -1e30f, mxb = -1e30f;
#pragma unroll
            for (int e = 0; e < 16; e += 2) {
                float a = sg[(rb + e) * 16 + f];
                float bq = sg[(rb + e + 1) * 16 + f];
                sa += a;  qa = fmaf(a, a, qa);  mna = fminf(mna, a);  mxa = fmaxf(mxa, a);
                sb += bq; qb = fmaf(bq, bq, qb); mnb = fminf(mnb, bq); mxb = fmaxf(mxb, bq);
            }
            float sum = sa + sb, sq = qa + qb;
            float mn = fminf(mna, mnb), mx = fmaxf(mxa, mxb);
            float mean = sum * (1.f / 16.f), m2 = sq * (1.f / 16.f);
            float st = sqrtf(fmaxf(m2 - mean * mean, 0.f) + EPS);
            int nd = lane >> 4;
            s_agg[w][nd][f]      = mean;
            s_agg[w][nd][16 + f] = mn;
            s_agg[w][nd][36 + f] = mx;
            s_agg[w][nd][52 + f] = st;
        }
        __syncwarp();
        int nA = (grp * 8 + w) * 2;
        {
            const float4* ar = (const float4*)&s_agg[w][node][hf * 36];
            float4 a4 = make_float4(0.f, 0.f, 0.f, 0.f);
#pragma unroll
            for (int j = 0; j < 8; j++) {
                float4 av = ar[j];
                a4.x = fmaf(Wr[j].x, av.x, a4.x); a4.y = fmaf(Wr[j].y, av.y, a4.y);
                a4.z = fmaf(Wr[j].z, av.z, a4.z); a4.w = fmaf(Wr[j].w, av.w, a4.w);
            }
            float p = (a4.x + a4.y) + (a4.z + a4.w);
            p += __shfl_xor_sync(0xffffffffu, p, 1);
            if (hf == 0) {
                float h = fmaxf(p + d2_c, 0.f);
                atomicAdd(&g_pooled[((nA + node) / NPG) * 8 + o], h);
            }
        }
        __syncwarp();

        if (!has_next) break;
        grp = grp_n; grp_n = grp_nn;
        d2_c = d2_n; d2_n = d2_nn; sv_n = sv_nn;
        buf ^= 1;
    }

    // ---- fused final: last block computes FC + log_softmax ----
    __syncthreads();
    __threadfence();
    if (t == 0) s_rank = atomicAdd(&g_ctr, 1u);
    __syncthreads();
    if (s_rank == (unsigned)(gridDim.x - 1)) {
        if (t == 0) g_ctr = 0;
        float w0[8], w1[8];
#pragma unroll
        for (int j = 0; j < 8; j++) { w0[j] = fc_w[j]; w1[j] = fc_w[8 + j]; }
        float b0 = fc_b[0], b1 = fc_b[1];
        for (int g = t; g < GG; g += 256) {
            volatile float* pp = &g_pooled[g * 8];
            float l0 = b0, l1 = b1;
#pragma unroll
            for (int j = 0; j < 8; j++) {
                float p = pp[j];
                l0 = fmaf(p, w0[j], l0);
                l1 = fmaf(p, w1[j], l1);
            }
            float m = fmaxf(l0, l1);
            float lse = m + logf(expf(l0 - m) + expf(l1 - m));
            out[g * 2 + 0] = l0 - lse;
            out[g * 2 + 1] = l1 - lse;
        }
    }
}

// ---------------- launch ----------------
extern "C" void kernel_launch(void* const* d_in, const int* in_sizes, int n_in,
                              void* d_out, int out_size)
{
    const float* x       = (const float*)d_in[0];
    const int*   src     = (const int*)d_in[1];
    const float* w1_pre  = (const float*)d_in[3];
    const float* b1_pre  = (const float*)d_in[4];
    const float* w1_post = (const float*)d_in[5];
    const float* b1_post = (const float*)d_in[6];
    const float* w1_lin  = (const float*)d_in[7];
    const float* b1_lin  = (const float*)d_in[8];
    const float* w2_pre  = (const float*)d_in[9];
    const float* b2_pre  = (const float*)d_in[10];
    const float* w2_post = (const float*)d_in[11];
    const float* b2_post = (const float*)d_in[12];
    const float* w2_lin  = (const float*)d_in[13];
    const float* b2_lin  = (const float*)d_in[14];
    const float* fc_w    = (const float*)d_in[15];
    const float* fc_b    = (const float*)d_in[16];
    float* out = (float*)d_out;

    fold_kernel<<<1, 256>>>(w1_pre, b1_pre, w1_post, b1_post, w1_lin, b1_lin);
    ab1_kernel<<<(NN + 255) / 256, 256>>>(x);
    conv1_kernel<<<CGRID1, 256>>>(src, w1_post, w1_lin,
                                  w2_pre, b2_pre, w2_post, b2_post, w2_lin, b2_lin);
    conv2_kernel<<<CGRID2, 256>>>(src, w2_post, w2_lin, fc_w, fc_b, out);
}